// round 16
// baseline (speedup 1.0000x reference)
#include <cuda_runtime.h>
#include <cuda_fp16.h>
#include <stdint.h>

#define N_TOK_TOTAL 16384
#define DPROJ 1024
#define EMB_SCALE 32.0f

// ---------------- device scratch (no allocations allowed) ----------------
// g_ctrl[0..3] = per-cluster counts, g_ctrl[4] = work-queue head
__device__ int g_ctrl[8];
__device__ int g_list[4][N_TOK_TOTAL];   // flat token index (output row)

// fp16 operand scratch: A = gathered emb rows in partition order, B = proj
__device__ __half gA0[N_TOK_TOTAL * 1024];
__device__ __half gA1[N_TOK_TOTAL * 256];
__device__ __half gA2[N_TOK_TOTAL * 64];
__device__ __half gA3[N_TOK_TOTAL * 16];
__device__ __half gB0[1024 * 1024];
__device__ __half gB1[1024 * 256];
__device__ __half gB2[1024 * 64];
__device__ __half gB3[1024 * 16];

// ------- setup: partition+gather (blocks 0-255, 64 tok each), proj (256-319)
__global__ __launch_bounds__(256)
void setup_kernel(const int* __restrict__ inp,
                  const float* __restrict__ e0, const float* __restrict__ e1,
                  const float* __restrict__ e2, const float* __restrict__ e3,
                  const float* __restrict__ p0, const float* __restrict__ p1,
                  const float* __restrict__ p2, const float* __restrict__ p3)
{
    const int tid = threadIdx.x;
    if (blockIdx.x < 256) {
        __shared__ int sCnt[4], sBase[4];
        __shared__ int sC[64], sPos[64], sRow[64];
        if (tid < 4) sCnt[tid] = 0;
        __syncthreads();

        if (tid < 64) {
            const int t = blockIdx.x * 64 + tid;
            const int idx = inp[t];
            int c, l;
            if (idx < 20000)      { c = 0; l = 0; }
            else if (idx < 40000) { c = 1; l = 20000; }
            else if (idx < 200000){ c = 2; l = 40000; }
            else                  { c = 3; l = 200000; }
            sC[tid] = c; sRow[tid] = idx - l;
            sPos[tid] = atomicAdd(&sCnt[c], 1);
        }
        __syncthreads();
        if (tid < 4) sBase[tid] = atomicAdd(&g_ctrl[tid], sCnt[tid]);
        __syncthreads();
        if (tid < 64) {
            const int pos = sBase[sC[tid]] + sPos[tid];
            sPos[tid] = pos;
            g_list[sC[tid]][pos] = blockIdx.x * 64 + tid;
        }
        __syncthreads();

        // cooperative gather: warp w -> rows w, w+8, ... (8 rows each)
        const int wid = tid >> 5, lid = tid & 31;
        for (int i = wid; i < 64; i += 8) {
            const int c2 = sC[i];
            const int p  = sPos[i];
            const int r  = sRow[i];
            const float* emb = (c2 == 0) ? e0 : (c2 == 1) ? e1 : (c2 == 2) ? e2 : e3;
            __half* ga = (c2 == 0) ? gA0 : (c2 == 1) ? gA1 : (c2 == 2) ? gA2 : gA3;
            const int K = 1024 >> (2 * c2);
            const int KQ = K >> 2;
            const float* src = emb + (size_t)r * K;
            __half* dst = ga + (size_t)p * K;
#pragma unroll 4
            for (int q = lid; q < KQ; q += 32) {
                float4 v = *(const float4*)(src + q * 4);
                __half2 h0 = __floats2half2_rn(v.x, v.y);
                __half2 h1 = __floats2half2_rn(v.z, v.w);
                uint2 w = make_uint2(*(uint32_t*)&h0, *(uint32_t*)&h1);
                *(uint2*)(dst + q * 4) = w;
            }
        }
    } else {
        const int bx = blockIdx.x - 256;       // 0..63
        const int c = bx >> 4;                 // 16 blocks per cluster
        const int rbase = (bx & 15) * 64;      // proj rows
        const float* proj = (c == 0) ? p0 : (c == 1) ? p1 : (c == 2) ? p2 : p3;
        __half* gb = (c == 0) ? gB0 : (c == 1) ? gB1 : (c == 2) ? gB2 : gB3;
        const int lgKQ = 8 - 2 * c;
        const int K = 4 << lgKQ;
        const int KQ = K >> 2;
        for (int t = tid; t < 64 * KQ; t += 256) {
            int r = rbase + (t >> lgKQ), q = t & (KQ - 1);
            float4 v = *(const float4*)(proj + (size_t)r * K + q * 4);
            __half2 h0 = __floats2half2_rn(v.x, v.y);
            __half2 h1 = __floats2half2_rn(v.z, v.w);
            uint2 w = make_uint2(*(uint32_t*)&h0, *(uint32_t*)&h1);
            *(uint2*)(gb + (size_t)r * K + q * 4) = w;
        }
    }
}

// ------------ persistent work-queue fp16 GEMM: 128x128 tiles, 2-stage -----
// Work item w -> (cluster, m-tile, n-tile); c0 items first (deep K spreads
// across SMs), then c1, c2, c3. 296 blocks, 2 per SM.
// 8 warps 4(M) x 2(N); warp tile 32x64 via m16n8k16 (fp32 accum).
// smem rows = 64 halves (128 B), XOR-swizzled 16B chunks: phys = kq ^ (row&7).
__global__ __launch_bounds__(256, 2)
void fused_gemm_tc(float* __restrict__ out)
{
    __shared__ __half sA[2][128 * 64];     // 2 x 16 KB
    __shared__ __half sB[2][128 * 64];     // 2 x 16 KB
    __shared__ int sW;

    const int cnt[4] = { g_ctrl[0], g_ctrl[1], g_ctrl[2], g_ctrl[3] };
    int e[4];
    {
        int acc = 0;
#pragma unroll
        for (int i = 0; i < 4; i++) {
            acc += ((cnt[i] + 127) >> 7) * 8;
            e[i] = acc;
        }
    }

    const int tid = threadIdx.x;
    const int wid = tid >> 5;
    const int lid = tid & 31;
    const int wy = wid & 3;          // M warp coord (x32)
    const int wx = wid >> 2;         // N warp coord (x64)
    const int tig = lid & 3;
    const int g = lid >> 2;
    const int rowS = tid >> 3;       // cp.async row slot (+j*32)
    const int kq = tid & 7;
    const int phys = kq ^ (rowS & 7);
    const int lmRow = lid & 15;
    const int lmSel = lid >> 4;

    while (true) {
        if (tid == 0) sW = atomicAdd(&g_ctrl[4], 1);
        __syncthreads();
        const int w = sW;
        if (w >= e[3]) break;

        int c, t;
        if (w < e[0])      { c = 0; t = w; }
        else if (w < e[1]) { c = 1; t = w - e[0]; }
        else if (w < e[2]) { c = 2; t = w - e[1]; }
        else               { c = 3; t = w - e[2]; }
        const int m0 = (t >> 3) * 128;
        const int n0 = (t & 7) * 128;
        const int count = cnt[c];

        const __half* ga = (c == 0) ? gA0 : (c == 1) ? gA1 : (c == 2) ? gA2 : gA3;
        const __half* gb = (c == 0) ? gB0 : (c == 1) ? gB1 : (c == 2) ? gB2 : gB3;
        const int K = 1024 >> (2 * c);
        const int nchunk = (K + 63) >> 6;

        float acc[2][8][4];
#pragma unroll
        for (int mf = 0; mf < 2; mf++)
#pragma unroll
            for (int nf = 0; nf < 8; nf++)
#pragma unroll
                for (int q = 0; q < 4; q++) acc[mf][nf][q] = 0.0f;

        auto prefetch = [&](int ch, int st) {
            const int kh = (ch << 6) + kq * 8;
            const bool kok = kh < K;
            const int vb = kok ? 16 : 0;
#pragma unroll
            for (int j = 0; j < 4; j++) {
                int m = rowS + j * 32;
                uint32_t dst = (uint32_t)__cvta_generic_to_shared(
                    &sA[st][m * 64 + phys * 8]);
                const __half* src = kok ? ga + (size_t)(m0 + m) * K + kh : ga;
                asm volatile("cp.async.cg.shared.global [%0], [%1], 16, %2;"
                             :: "r"(dst), "l"(src), "r"(vb));
            }
#pragma unroll
            for (int j = 0; j < 4; j++) {
                int n = rowS + j * 32;
                uint32_t dst = (uint32_t)__cvta_generic_to_shared(
                    &sB[st][n * 64 + phys * 8]);
                const __half* src = kok ? gb + (size_t)(n0 + n) * K + kh : gb;
                asm volatile("cp.async.cg.shared.global [%0], [%1], 16, %2;"
                             :: "r"(dst), "l"(src), "r"(vb));
            }
            asm volatile("cp.async.commit_group;" ::: "memory");
        };

        prefetch(0, 0);

        for (int ch = 0; ch < nchunk; ch++) {
            const bool more = (ch + 1) < nchunk;
            if (more) prefetch(ch + 1, (ch + 1) & 1);
            if (more) asm volatile("cp.async.wait_group 1;" ::: "memory");
            else      asm volatile("cp.async.wait_group 0;" ::: "memory");
            __syncthreads();

            const int buf = ch & 1;
            const uint32_t baseA = (uint32_t)__cvta_generic_to_shared(sA[buf]);
            const uint32_t baseB = (uint32_t)__cvta_generic_to_shared(sB[buf]);
#pragma unroll
            for (int ks = 0; ks < 4; ks++) {
                uint32_t A[2][4], B[8][2];
#pragma unroll
                for (int mf = 0; mf < 2; mf++) {
                    int row = wy * 32 + mf * 16 + lmRow;
                    int chk = (2 * ks + lmSel) ^ (row & 7);
                    uint32_t addr = baseA + (uint32_t)(row * 128 + chk * 16);
                    asm volatile("ldmatrix.sync.aligned.m8n8.x4.shared.b16 {%0,%1,%2,%3}, [%4];"
                                 : "=r"(A[mf][0]), "=r"(A[mf][1]), "=r"(A[mf][2]), "=r"(A[mf][3])
                                 : "r"(addr));
                }
#pragma unroll
                for (int nf2 = 0; nf2 < 4; nf2++) {
                    int row = wx * 64 + nf2 * 16 + lmRow;
                    int chk = (2 * ks + lmSel) ^ (row & 7);
                    uint32_t addr = baseB + (uint32_t)(row * 128 + chk * 16);
                    uint32_t r0, r1, r2, r3;
                    asm volatile("ldmatrix.sync.aligned.m8n8.x4.shared.b16 {%0,%1,%2,%3}, [%4];"
                                 : "=r"(r0), "=r"(r1), "=r"(r2), "=r"(r3)
                                 : "r"(addr));
                    B[nf2 * 2 + 0][0] = r0;  B[nf2 * 2 + 1][0] = r1;
                    B[nf2 * 2 + 0][1] = r2;  B[nf2 * 2 + 1][1] = r3;
                }
#pragma unroll
                for (int mf = 0; mf < 2; mf++)
#pragma unroll
                    for (int nf = 0; nf < 8; nf++) {
                        asm volatile(
                            "mma.sync.aligned.m16n8k16.row.col.f32.f16.f16.f32 "
                            "{%0,%1,%2,%3}, {%4,%5,%6,%7}, {%8,%9}, {%0,%1,%2,%3};"
                            : "+f"(acc[mf][nf][0]), "+f"(acc[mf][nf][1]),
                              "+f"(acc[mf][nf][2]), "+f"(acc[mf][nf][3])
                            : "r"(A[mf][0]), "r"(A[mf][1]), "r"(A[mf][2]), "r"(A[mf][3]),
                              "r"(B[nf][0]), "r"(B[nf][1]));
                    }
            }
            __syncthreads();   // all reads of buf done before it is refilled
        }

        // ---- epilogue: scatter rows via g_list
#pragma unroll
        for (int mf = 0; mf < 2; mf++) {
            int r0 = m0 + wy * 32 + mf * 16 + g;
            int r1 = r0 + 8;
            bool v0 = r0 < count, v1 = r1 < count;
            float* o0 = v0 ? out + (size_t)g_list[c][r0] * DPROJ + n0 : nullptr;
            float* o1 = v1 ? out + (size_t)g_list[c][r1] * DPROJ + n0 : nullptr;
#pragma unroll
            for (int nf = 0; nf < 8; nf++) {
                int col = wx * 64 + nf * 8 + 2 * tig;
                if (v0) {
                    float2 wv = make_float2(acc[mf][nf][0] * EMB_SCALE,
                                            acc[mf][nf][1] * EMB_SCALE);
                    *(float2*)(o0 + col) = wv;
                }
                if (v1) {
                    float2 wv = make_float2(acc[mf][nf][2] * EMB_SCALE,
                                            acc[mf][nf][3] * EMB_SCALE);
                    *(float2*)(o1 + col) = wv;
                }
            }
        }
        __syncthreads();   // everyone done with sW before next fetch
    }
}

// ---------------- host entry ----------------
extern "C" void kernel_launch(void* const* d_in, const int* in_sizes, int n_in,
                              void* d_out, int out_size) {
    // Map inputs by element count (robust to metadata ordering).
    const int* inp = (const int*)d_in[0];
    const float *emb[4] = {0, 0, 0, 0}, *proj[4] = {0, 0, 0, 0};
    for (int i = 1; i < n_in; i++) {
        long sz = in_sizes[i];
        const float* p = (const float*)d_in[i];
        switch (sz) {
            case 20000L * 1024:  emb[0]  = p; break;
            case 1024L * 1024:   proj[0] = p; break;
            case 20000L * 256:   emb[1]  = p; break;
            case 1024L * 256:    proj[1] = p; break;
            case 160000L * 64:   emb[2]  = p; break;
            case 1024L * 64:     proj[2] = p; break;
            case 67735L * 16:    emb[3]  = p; break;
            case 1024L * 16:     proj[3] = p; break;
            default: break;
        }
    }
    float* out = (float*)d_out;

    void* gctrl = nullptr;
    cudaGetSymbolAddress(&gctrl, g_ctrl);
    cudaMemsetAsync(gctrl, 0, 8 * sizeof(int), 0);

    setup_kernel<<<320, 256>>>(inp, emb[0], emb[1], emb[2], emb[3],
                               proj[0], proj[1], proj[2], proj[3]);

    fused_gemm_tc<<<296, 256>>>(out);
}

// round 17
// speedup vs baseline: 1.5764x; 1.5764x over previous
#include <cuda_runtime.h>
#include <cuda_fp16.h>
#include <stdint.h>

#define N_TOK_TOTAL 16384
#define DPROJ 1024
#define EMB_SCALE 32.0f

// ---------------- device scratch (no allocations allowed) ----------------
__device__ int g_ctrl[8];                // [0..3] = per-cluster counts
__device__ int g_list[4][N_TOK_TOTAL];   // flat token index (output row)

// fp16 operand scratch: A = gathered emb rows in partition order, B = proj
__device__ __half gA0[N_TOK_TOTAL * 1024];
__device__ __half gA1[N_TOK_TOTAL * 256];
__device__ __half gA2[N_TOK_TOTAL * 64];
__device__ __half gA3[N_TOK_TOTAL * 16];
__device__ __half gB0[1024 * 1024];
__device__ __half gB1[1024 * 256];
__device__ __half gB2[1024 * 64];
__device__ __half gB3[1024 * 16];

// ------- setup: partition+gather (blocks 0-255, 64 tok each), proj (256-319)
__global__ __launch_bounds__(256)
void setup_kernel(const int* __restrict__ inp,
                  const float* __restrict__ e0, const float* __restrict__ e1,
                  const float* __restrict__ e2, const float* __restrict__ e3,
                  const float* __restrict__ p0, const float* __restrict__ p1,
                  const float* __restrict__ p2, const float* __restrict__ p3)
{
    const int tid = threadIdx.x;
    if (blockIdx.x < 256) {
        __shared__ int sCnt[4], sBase[4];
        __shared__ int sC[64], sPos[64], sRow[64];
        if (tid < 4) sCnt[tid] = 0;
        __syncthreads();

        if (tid < 64) {
            const int t = blockIdx.x * 64 + tid;
            const int idx = inp[t];
            int c, l;
            if (idx < 20000)      { c = 0; l = 0; }
            else if (idx < 40000) { c = 1; l = 20000; }
            else if (idx < 200000){ c = 2; l = 40000; }
            else                  { c = 3; l = 200000; }
            sC[tid] = c; sRow[tid] = idx - l;
            sPos[tid] = atomicAdd(&sCnt[c], 1);
        }
        __syncthreads();
        if (tid < 4) sBase[tid] = atomicAdd(&g_ctrl[tid], sCnt[tid]);
        __syncthreads();
        if (tid < 64) {
            const int pos = sBase[sC[tid]] + sPos[tid];
            sPos[tid] = pos;
            g_list[sC[tid]][pos] = blockIdx.x * 64 + tid;
        }
        __syncthreads();

        // cooperative gather: warp w -> rows w, w+8, ... (8 rows each)
        const int wid = tid >> 5, lid = tid & 31;
        for (int i = wid; i < 64; i += 8) {
            const int c2 = sC[i];
            const int p  = sPos[i];
            const int r  = sRow[i];
            const float* emb = (c2 == 0) ? e0 : (c2 == 1) ? e1 : (c2 == 2) ? e2 : e3;
            __half* ga = (c2 == 0) ? gA0 : (c2 == 1) ? gA1 : (c2 == 2) ? gA2 : gA3;
            const int K = 1024 >> (2 * c2);
            const int KQ = K >> 2;
            const float* src = emb + (size_t)r * K;
            __half* dst = ga + (size_t)p * K;
#pragma unroll 4
            for (int q = lid; q < KQ; q += 32) {
                float4 v = *(const float4*)(src + q * 4);
                __half2 h0 = __floats2half2_rn(v.x, v.y);
                __half2 h1 = __floats2half2_rn(v.z, v.w);
                uint2 w = make_uint2(*(uint32_t*)&h0, *(uint32_t*)&h1);
                *(uint2*)(dst + q * 4) = w;
            }
        }
    } else {
        const int bx = blockIdx.x - 256;       // 0..63
        const int c = bx >> 4;                 // 16 blocks per cluster
        const int rbase = (bx & 15) * 64;      // proj rows
        const float* proj = (c == 0) ? p0 : (c == 1) ? p1 : (c == 2) ? p2 : p3;
        __half* gb = (c == 0) ? gB0 : (c == 1) ? gB1 : (c == 2) ? gB2 : gB3;
        const int lgKQ = 8 - 2 * c;
        const int K = 4 << lgKQ;
        const int KQ = K >> 2;
        for (int t = tid; t < 64 * KQ; t += 256) {
            int r = rbase + (t >> lgKQ), q = t & (KQ - 1);
            float4 v = *(const float4*)(proj + (size_t)r * K + q * 4);
            __half2 h0 = __floats2half2_rn(v.x, v.y);
            __half2 h1 = __floats2half2_rn(v.z, v.w);
            uint2 w = make_uint2(*(uint32_t*)&h0, *(uint32_t*)&h1);
            *(uint2*)(gb + (size_t)r * K + q * 4) = w;
        }
    }
}

// ---- dense fp16 GEMM: tight 1-D grid, on-device tile decode, 3-stage -----
// Block w -> (cluster, m-tile, n-tile) via prefix of ceil(count/128)*8;
// c0 tiles first. Worst-case total tiles <= 1048 for any input.
// 8 warps 4(M) x 2(N); warp tile 32x64 via m16n8k16 (fp32 accum).
// smem rows = 64 halves (128 B), XOR-swizzled 16B chunks: phys = kq ^ (row&7).
__global__ __launch_bounds__(256)
void fused_gemm_tc(float* __restrict__ out)
{
    __shared__ __half sA[3][128 * 64];     // 3 x 16 KB
    __shared__ __half sB[3][128 * 64];     // 3 x 16 KB

    const int cnt0 = g_ctrl[0], cnt1 = g_ctrl[1], cnt2 = g_ctrl[2], cnt3 = g_ctrl[3];
    const int e0 = ((cnt0 + 127) >> 7) * 8;
    const int e1 = e0 + ((cnt1 + 127) >> 7) * 8;
    const int e2 = e1 + ((cnt2 + 127) >> 7) * 8;
    const int e3 = e2 + ((cnt3 + 127) >> 7) * 8;

    const int w = blockIdx.x;
    if (w >= e3) return;
    int c, t;
    if (w < e0)      { c = 0; t = w; }
    else if (w < e1) { c = 1; t = w - e0; }
    else if (w < e2) { c = 2; t = w - e1; }
    else             { c = 3; t = w - e2; }
    const int m0 = (t >> 3) * 128;
    const int n0 = (t & 7) * 128;
    const int count = (c == 0) ? cnt0 : (c == 1) ? cnt1 : (c == 2) ? cnt2 : cnt3;

    const __half* ga = (c == 0) ? gA0 : (c == 1) ? gA1 : (c == 2) ? gA2 : gA3;
    const __half* gb = (c == 0) ? gB0 : (c == 1) ? gB1 : (c == 2) ? gB2 : gB3;
    const int K = 1024 >> (2 * c);
    const int nchunk = (K + 63) >> 6;

    const int tid = threadIdx.x;
    const int wid = tid >> 5;
    const int lid = tid & 31;
    const int wy = wid & 3;          // M warp coord (x32)
    const int wx = wid >> 2;         // N warp coord (x64)
    const int tig = lid & 3;
    const int g = lid >> 2;
    const int rowS = tid >> 3;       // cp.async row slot (+j*32)
    const int kq = tid & 7;
    const int phys = kq ^ (rowS & 7);      // swizzled 16B chunk
    const int lmRow = lid & 15;
    const int lmSel = lid >> 4;            // 0/1: +16B within 32B k-group

    float acc[2][8][4];
#pragma unroll
    for (int mf = 0; mf < 2; mf++)
#pragma unroll
        for (int nf = 0; nf < 8; nf++)
#pragma unroll
            for (int q = 0; q < 4; q++) acc[mf][nf][q] = 0.0f;

    auto prefetch = [&](int ch, int st) {
        if (ch < nchunk) {
            const int kh = (ch << 6) + kq * 8;
            const bool kok = kh < K;
            const int vb = kok ? 16 : 0;
#pragma unroll
            for (int j = 0; j < 4; j++) {
                int m = rowS + j * 32;
                uint32_t dst = (uint32_t)__cvta_generic_to_shared(
                    &sA[st][m * 64 + phys * 8]);
                const __half* src = kok ? ga + (size_t)(m0 + m) * K + kh : ga;
                asm volatile("cp.async.cg.shared.global [%0], [%1], 16, %2;"
                             :: "r"(dst), "l"(src), "r"(vb));
            }
#pragma unroll
            for (int j = 0; j < 4; j++) {
                int n = rowS + j * 32;
                uint32_t dst = (uint32_t)__cvta_generic_to_shared(
                    &sB[st][n * 64 + phys * 8]);
                const __half* src = kok ? gb + (size_t)(n0 + n) * K + kh : gb;
                asm volatile("cp.async.cg.shared.global [%0], [%1], 16, %2;"
                             :: "r"(dst), "l"(src), "r"(vb));
            }
        }
        asm volatile("cp.async.commit_group;" ::: "memory");
    };

    prefetch(0, 0);
    prefetch(1, 1);

    for (int ch = 0; ch < nchunk; ch++) {
        asm volatile("cp.async.wait_group 1;" ::: "memory");
        __syncthreads();

        const int buf = ch % 3;
        const uint32_t baseA = (uint32_t)__cvta_generic_to_shared(sA[buf]);
        const uint32_t baseB = (uint32_t)__cvta_generic_to_shared(sB[buf]);
#pragma unroll
        for (int ks = 0; ks < 4; ks++) {
            uint32_t A[2][4], B[8][2];
#pragma unroll
            for (int mf = 0; mf < 2; mf++) {
                int row = wy * 32 + mf * 16 + lmRow;
                int chk = (2 * ks + lmSel) ^ (row & 7);
                uint32_t addr = baseA + (uint32_t)(row * 128 + chk * 16);
                asm volatile("ldmatrix.sync.aligned.m8n8.x4.shared.b16 {%0,%1,%2,%3}, [%4];"
                             : "=r"(A[mf][0]), "=r"(A[mf][1]), "=r"(A[mf][2]), "=r"(A[mf][3])
                             : "r"(addr));
            }
#pragma unroll
            for (int nf2 = 0; nf2 < 4; nf2++) {
                int row = wx * 64 + nf2 * 16 + lmRow;
                int chk = (2 * ks + lmSel) ^ (row & 7);
                uint32_t addr = baseB + (uint32_t)(row * 128 + chk * 16);
                uint32_t r0, r1, r2, r3;
                asm volatile("ldmatrix.sync.aligned.m8n8.x4.shared.b16 {%0,%1,%2,%3}, [%4];"
                             : "=r"(r0), "=r"(r1), "=r"(r2), "=r"(r3)
                             : "r"(addr));
                B[nf2 * 2 + 0][0] = r0;  B[nf2 * 2 + 1][0] = r1;
                B[nf2 * 2 + 0][1] = r2;  B[nf2 * 2 + 1][1] = r3;
            }
#pragma unroll
            for (int mf = 0; mf < 2; mf++)
#pragma unroll
                for (int nf = 0; nf < 8; nf++) {
                    asm volatile(
                        "mma.sync.aligned.m16n8k16.row.col.f32.f16.f16.f32 "
                        "{%0,%1,%2,%3}, {%4,%5,%6,%7}, {%8,%9}, {%0,%1,%2,%3};"
                        : "+f"(acc[mf][nf][0]), "+f"(acc[mf][nf][1]),
                          "+f"(acc[mf][nf][2]), "+f"(acc[mf][nf][3])
                        : "r"(A[mf][0]), "r"(A[mf][1]), "r"(A[mf][2]), "r"(A[mf][3]),
                          "r"(B[nf][0]), "r"(B[nf][1]));
                }
        }
        prefetch(ch + 2, (ch + 2) % 3);
    }

    // ---- epilogue: scatter rows via g_list
#pragma unroll
    for (int mf = 0; mf < 2; mf++) {
        int r0 = m0 + wy * 32 + mf * 16 + g;
        int r1 = r0 + 8;
        bool v0 = r0 < count, v1 = r1 < count;
        float* o0 = v0 ? out + (size_t)g_list[c][r0] * DPROJ + n0 : nullptr;
        float* o1 = v1 ? out + (size_t)g_list[c][r1] * DPROJ + n0 : nullptr;
#pragma unroll
        for (int nf = 0; nf < 8; nf++) {
            int col = wx * 64 + nf * 8 + 2 * tig;
            if (v0) {
                float2 wv = make_float2(acc[mf][nf][0] * EMB_SCALE,
                                        acc[mf][nf][1] * EMB_SCALE);
                *(float2*)(o0 + col) = wv;
            }
            if (v1) {
                float2 wv = make_float2(acc[mf][nf][2] * EMB_SCALE,
                                        acc[mf][nf][3] * EMB_SCALE);
                *(float2*)(o1 + col) = wv;
            }
        }
    }
}

// ---------------- host entry ----------------
extern "C" void kernel_launch(void* const* d_in, const int* in_sizes, int n_in,
                              void* d_out, int out_size) {
    // Map inputs by element count (robust to metadata ordering).
    const int* inp = (const int*)d_in[0];
    const float *emb[4] = {0, 0, 0, 0}, *proj[4] = {0, 0, 0, 0};
    for (int i = 1; i < n_in; i++) {
        long sz = in_sizes[i];
        const float* p = (const float*)d_in[i];
        switch (sz) {
            case 20000L * 1024:  emb[0]  = p; break;
            case 1024L * 1024:   proj[0] = p; break;
            case 20000L * 256:   emb[1]  = p; break;
            case 1024L * 256:    proj[1] = p; break;
            case 160000L * 64:   emb[2]  = p; break;
            case 1024L * 64:     proj[2] = p; break;
            case 67735L * 16:    emb[3]  = p; break;
            case 1024L * 16:     proj[3] = p; break;
            default: break;
        }
    }
    float* out = (float*)d_out;

    void* gctrl = nullptr;
    cudaGetSymbolAddress(&gctrl, g_ctrl);
    cudaMemsetAsync(gctrl, 0, 8 * sizeof(int), 0);

    setup_kernel<<<320, 256>>>(inp, emb[0], emb[1], emb[2], emb[3],
                               proj[0], proj[1], proj[2], proj[3]);

    // worst-case tile count: sum ceil(count_i/128) <= 131 m-tiles -> 1048 tiles
    fused_gemm_tc<<<1056, 256>>>(out);
}